// round 2
// baseline (speedup 1.0000x reference)
#include <cuda_runtime.h>
#include <cuda_bf16.h>
#include <cstdint>

// ===================== problem dims / tiles =====================
static constexpr int T     = 4096;   // tokens (M)
static constexpr int IN_F  = 4096;   // K
static constexpr int OUT_F = 4096;   // N
static constexpr int KC    = 64;     // K chunk bytes (int8)
static constexpr int KITERS = IN_F / KC;   // 64
static constexpr int ROWB  = 80;     // smem row stride (conflict-free ldmatrix)

// ===================== device scratch =====================
__device__ float g_partial[1024];
__device__ float g_scale;
__device__ float g_inv;
__device__ __align__(16) int8_t g_qx[(size_t)T * IN_F];     // 16MB quantized activations
__device__ __align__(16) int8_t g_wt[(size_t)OUT_F * IN_F]; // 16MB int8 weights

// ===================== helpers =====================
__device__ __forceinline__ uint32_t smem_u32(const void* p) {
    uint32_t a;
    asm("{ .reg .u64 t; cvta.to.shared.u64 t, %1; cvt.u32.u64 %0, t; }" : "=r"(a) : "l"(p));
    return a;
}
__device__ __forceinline__ void ldsm_x4(uint32_t* r, uint32_t addr) {
    asm volatile("ldmatrix.sync.aligned.m8n8.x4.shared.b16 {%0,%1,%2,%3}, [%4];"
                 : "=r"(r[0]), "=r"(r[1]), "=r"(r[2]), "=r"(r[3]) : "r"(addr));
}
__device__ __forceinline__ void mma_s8(int* c, const uint32_t* a, const uint32_t* b) {
    asm volatile(
        "mma.sync.aligned.m16n8k32.row.col.s32.s8.s8.s32 "
        "{%0,%1,%2,%3}, {%4,%5,%6,%7}, {%8,%9}, {%0,%1,%2,%3};"
        : "+r"(c[0]), "+r"(c[1]), "+r"(c[2]), "+r"(c[3])
        : "r"(a[0]), "r"(a[1]), "r"(a[2]), "r"(a[3]), "r"(b[0]), "r"(b[1]));
}

// ===================== stage 1: max|x| =====================
__global__ void k_maxabs(const float* __restrict__ x) {
    __shared__ float red[256];
    float m = 0.f;
    const float4* x4 = (const float4*)x;
    const int n4 = T * IN_F / 4;
    for (int i = blockIdx.x * blockDim.x + threadIdx.x; i < n4; i += gridDim.x * blockDim.x) {
        float4 v = x4[i];
        m = fmaxf(m, fmaxf(fmaxf(fabsf(v.x), fabsf(v.y)), fmaxf(fabsf(v.z), fabsf(v.w))));
    }
    red[threadIdx.x] = m;
    __syncthreads();
    #pragma unroll
    for (int s = 128; s > 0; s >>= 1) {
        if (threadIdx.x < s) red[threadIdx.x] = fmaxf(red[threadIdx.x], red[threadIdx.x + s]);
        __syncthreads();
    }
    if (threadIdx.x == 0) g_partial[blockIdx.x] = red[0];
}

__global__ void k_finalize() {
    __shared__ float red[1024];
    red[threadIdx.x] = g_partial[threadIdx.x];
    __syncthreads();
    #pragma unroll
    for (int s = 512; s > 0; s >>= 1) {
        if (threadIdx.x < s) red[threadIdx.x] = fmaxf(red[threadIdx.x], red[threadIdx.x + s]);
        __syncthreads();
    }
    if (threadIdx.x == 0) {
        float sc = __fdiv_rn(red[0], 127.0f);
        g_scale = sc;
        g_inv = __fdiv_rn(1.0f, sc);
    }
}

// ===================== stage 2: quantize x -> int8 =====================
__global__ void k_quant(const float* __restrict__ x) {
    const float inv = g_inv;
    const float4* x4 = (const float4*)x;
    uint32_t* o = (uint32_t*)g_qx;
    const int n4 = T * IN_F / 4;
    for (int i = blockIdx.x * blockDim.x + threadIdx.x; i < n4; i += gridDim.x * blockDim.x) {
        float4 v = x4[i];
        // |x*inv| <= 127*(1+eps): round-to-nearest-even lands in [-127,127], no clamp.
        int q0 = __float2int_rn(v.x * inv);
        int q1 = __float2int_rn(v.y * inv);
        int q2 = __float2int_rn(v.z * inv);
        int q3 = __float2int_rn(v.w * inv);
        o[i] = (q0 & 0xFF) | ((q1 & 0xFF) << 8) | ((q2 & 0xFF) << 16) | ((uint32_t)(q3 & 0xFF) << 24);
    }
}

// ===================== stage 3: weight int32 -> int8 =====================
__global__ void k_wconv(const int* __restrict__ w) {
    const int4* w4 = (const int4*)w;
    uint32_t* o = (uint32_t*)g_wt;
    const int n4 = OUT_F * IN_F / 4;
    for (int i = blockIdx.x * blockDim.x + threadIdx.x; i < n4; i += gridDim.x * blockDim.x) {
        int4 v = w4[i];
        o[i] = (v.x & 0xFF) | ((v.y & 0xFF) << 8) | ((v.z & 0xFF) << 16) | ((uint32_t)(v.w & 0xFF) << 24);
    }
}

// ===================== stage 4: int8 mma.sync GEMM + epilogue =====================
// CTA 128x128, 8 warps in 2(M) x 4(N), warp tile 64x32.
__global__ void __launch_bounds__(256) k_gemm(const float* __restrict__ wscale,
                                              const float* __restrict__ bias,
                                              float* __restrict__ out) {
    // smem: [A buf0][A buf1][B buf0][B buf1], each 128 rows * 80B
    __shared__ __align__(16) char smem[4][128 * ROWB];

    const int tid  = threadIdx.x;
    const int lane = tid & 31;
    const int wid  = tid >> 5;
    const int mwarp = wid >> 2;     // 0..1
    const int nwarp = wid & 3;      // 0..3
    const int Mbase = blockIdx.y * 128;
    const int Nbase = blockIdx.x * 128;

    const int8_t* Ab = g_qx + (size_t)Mbase * IN_F;
    const int8_t* Bb = g_wt + (size_t)Nbase * IN_F;

    // global->smem staging: 2 x 16B chunks per thread per tile
    const int arow0 = tid >> 2;          // 0..63
    const int ac    = (tid & 3) * 16;    // byte col within 64B chunk
    const uint32_t soff0 = (uint32_t)arow0 * ROWB + ac;
    const uint32_t soff1 = soff0 + 64u * ROWB;

    const uint32_t sA[2] = { smem_u32(smem[0]), smem_u32(smem[1]) };
    const uint32_t sB[2] = { smem_u32(smem[2]), smem_u32(smem[3]) };

    // ldmatrix per-thread offsets
    const int tile = lane >> 3;
    const int sub  = lane & 7;
    uint32_t aoff[4], boff[2];
    #pragma unroll
    for (int mb = 0; mb < 4; ++mb)
        aoff[mb] = (uint32_t)(mwarp * 64 + mb * 16 + (tile & 1) * 8 + sub) * ROWB
                 + (uint32_t)(tile >> 1) * 16;
    #pragma unroll
    for (int p = 0; p < 2; ++p)
        boff[p] = (uint32_t)(nwarp * 32 + p * 16 + (tile >> 1) * 8 + sub) * ROWB
                 + (uint32_t)(tile & 1) * 16;

    int acc[4][4][4];
    #pragma unroll
    for (int mb = 0; mb < 4; ++mb)
        #pragma unroll
        for (int nb = 0; nb < 4; ++nb)
            #pragma unroll
            for (int f = 0; f < 4; ++f) acc[mb][nb][f] = 0;

    // prologue: load chunk 0 into buf 0
    {
        const int8_t* Ag = Ab;
        const int8_t* Bg = Bb;
        *(uint4*)(smem[0] + soff0) = *(const uint4*)(Ag + (size_t)arow0 * IN_F + ac);
        *(uint4*)(smem[0] + soff1) = *(const uint4*)(Ag + (size_t)(arow0 + 64) * IN_F + ac);
        *(uint4*)(smem[2] + soff0) = *(const uint4*)(Bg + (size_t)arow0 * IN_F + ac);
        *(uint4*)(smem[2] + soff1) = *(const uint4*)(Bg + (size_t)(arow0 + 64) * IN_F + ac);
    }
    __syncthreads();

    for (int it = 0; it < KITERS; ++it) {
        const int buf = it & 1;
        const bool pref = (it + 1 < KITERS);
        uint4 ra0, ra1, rb0, rb1;
        if (pref) {
            const int8_t* Ag = Ab + (it + 1) * KC;
            const int8_t* Bg = Bb + (it + 1) * KC;
            ra0 = *(const uint4*)(Ag + (size_t)arow0 * IN_F + ac);
            ra1 = *(const uint4*)(Ag + (size_t)(arow0 + 64) * IN_F + ac);
            rb0 = *(const uint4*)(Bg + (size_t)arow0 * IN_F + ac);
            rb1 = *(const uint4*)(Bg + (size_t)(arow0 + 64) * IN_F + ac);
        }

        // compute on buf: two K=32 steps
        #pragma unroll
        for (int ks = 0; ks < 2; ++ks) {
            uint32_t af[4][4];
            uint32_t bf[4][2];
            #pragma unroll
            for (int mb = 0; mb < 4; ++mb)
                ldsm_x4(af[mb], sA[buf] + aoff[mb] + ks * 32);
            #pragma unroll
            for (int p = 0; p < 2; ++p) {
                uint32_t r[4];
                ldsm_x4(r, sB[buf] + boff[p] + ks * 32);
                bf[p * 2 + 0][0] = r[0]; bf[p * 2 + 0][1] = r[1];
                bf[p * 2 + 1][0] = r[2]; bf[p * 2 + 1][1] = r[3];
            }
            #pragma unroll
            for (int mb = 0; mb < 4; ++mb)
                #pragma unroll
                for (int nb = 0; nb < 4; ++nb)
                    mma_s8(acc[mb][nb], af[mb], bf[nb]);
        }

        if (pref) {
            const int nbuf = buf ^ 1;
            *(uint4*)(smem[0 + nbuf] + soff0) = ra0;
            *(uint4*)(smem[0 + nbuf] + soff1) = ra1;
            *(uint4*)(smem[2 + nbuf] + soff0) = rb0;
            *(uint4*)(smem[2 + nbuf] + soff1) = rb1;
        }
        __syncthreads();
    }

    // epilogue: direct store, exact int32 -> fp32 scale + bias
    const float s = g_scale * wscale[0];
    const int g   = lane >> 2;
    const int tg2 = (lane & 3) * 2;
    #pragma unroll
    for (int nb = 0; nb < 4; ++nb) {
        const int col = Nbase + nwarp * 32 + nb * 8 + tg2;
        const float2 bb = *(const float2*)(bias + col);
        #pragma unroll
        for (int mb = 0; mb < 4; ++mb) {
            const int row = Mbase + mwarp * 64 + mb * 16 + g;
            float2 v0, v1;
            v0.x = fmaf((float)acc[mb][nb][0], s, bb.x);
            v0.y = fmaf((float)acc[mb][nb][1], s, bb.y);
            v1.x = fmaf((float)acc[mb][nb][2], s, bb.x);
            v1.y = fmaf((float)acc[mb][nb][3], s, bb.y);
            *(float2*)(out + (size_t)row * OUT_F + col)       = v0;
            *(float2*)(out + (size_t)(row + 8) * OUT_F + col) = v1;
        }
    }
}

// ===================== launch =====================
extern "C" void kernel_launch(void* const* d_in, const int* in_sizes, int n_in,
                              void* d_out, int out_size) {
    const float* x    = (const float*)d_in[0];
    const int*   qw   = (const int*)d_in[1];
    const float* ws   = (const float*)d_in[2];
    const float* bias = (const float*)d_in[3];
    float* out = (float*)d_out;

    k_maxabs<<<1024, 256>>>(x);
    k_finalize<<<1, 1024>>>();
    k_quant<<<1024, 256>>>(x);
    k_wconv<<<1024, 256>>>(qw);
    k_gemm<<<dim3(OUT_F / 128, T / 128), 256>>>(ws, bias, out);
}

// round 3
// speedup vs baseline: 1.0019x; 1.0019x over previous
#include <cuda_runtime.h>
#include <cuda_bf16.h>
#include <cstdint>

// ===================== problem dims / tiles =====================
static constexpr int T     = 4096;   // tokens (M)
static constexpr int IN_F  = 4096;   // K
static constexpr int OUT_F = 4096;   // N
static constexpr int KC    = 64;     // K chunk bytes (int8)
static constexpr int KITERS = IN_F / KC;   // 64
static constexpr int ROWB  = 80;     // smem row stride (conflict-free ldmatrix)
static constexpr int STAGES = 4;
static constexpr int SSTR  = 256 * ROWB;             // bytes per stage (A rows 0-127, B rows 128-255)
static constexpr int SMEM_TOTAL = STAGES * SSTR;     // 81920

// ===================== device scratch =====================
__device__ float g_partial[1024];
__device__ float g_scale;
__device__ float g_inv;
__device__ __align__(16) int8_t g_qx[(size_t)T * IN_F];     // 16MB quantized activations
__device__ __align__(16) int8_t g_wt[(size_t)OUT_F * IN_F]; // 16MB int8 weights

// ===================== helpers =====================
__device__ __forceinline__ uint32_t smem_u32(const void* p) {
    uint32_t a;
    asm("{ .reg .u64 t; cvta.to.shared.u64 t, %1; cvt.u32.u64 %0, t; }" : "=r"(a) : "l"(p));
    return a;
}
__device__ __forceinline__ void ldsm_x4(uint32_t* r, uint32_t addr) {
    asm volatile("ldmatrix.sync.aligned.m8n8.x4.shared.b16 {%0,%1,%2,%3}, [%4];"
                 : "=r"(r[0]), "=r"(r[1]), "=r"(r[2]), "=r"(r[3]) : "r"(addr));
}
__device__ __forceinline__ void mma_s8(int* c, const uint32_t* a, const uint32_t* b) {
    asm volatile(
        "mma.sync.aligned.m16n8k32.row.col.s32.s8.s8.s32 "
        "{%0,%1,%2,%3}, {%4,%5,%6,%7}, {%8,%9}, {%0,%1,%2,%3};"
        : "+r"(c[0]), "+r"(c[1]), "+r"(c[2]), "+r"(c[3])
        : "r"(a[0]), "r"(a[1]), "r"(a[2]), "r"(a[3]), "r"(b[0]), "r"(b[1]));
}
__device__ __forceinline__ void cp16(uint32_t saddr, const void* gaddr) {
    asm volatile("cp.async.cg.shared.global [%0], [%1], 16;" :: "r"(saddr), "l"(gaddr));
}
__device__ __forceinline__ void cp_commit() {
    asm volatile("cp.async.commit_group;" ::: "memory");
}
__device__ __forceinline__ void cp_wait2() {
    asm volatile("cp.async.wait_group 2;" ::: "memory");
}

// ===================== stage 1: max|x| =====================
__global__ void k_maxabs(const float* __restrict__ x) {
    __shared__ float red[256];
    float m = 0.f;
    const float4* x4 = (const float4*)x;
    const int n4 = T * IN_F / 4;
    for (int i = blockIdx.x * blockDim.x + threadIdx.x; i < n4; i += gridDim.x * blockDim.x) {
        float4 v = x4[i];
        m = fmaxf(m, fmaxf(fmaxf(fabsf(v.x), fabsf(v.y)), fmaxf(fabsf(v.z), fabsf(v.w))));
    }
    red[threadIdx.x] = m;
    __syncthreads();
    #pragma unroll
    for (int s = 128; s > 0; s >>= 1) {
        if (threadIdx.x < s) red[threadIdx.x] = fmaxf(red[threadIdx.x], red[threadIdx.x + s]);
        __syncthreads();
    }
    if (threadIdx.x == 0) g_partial[blockIdx.x] = red[0];
}

__global__ void k_finalize() {
    __shared__ float red[1024];
    red[threadIdx.x] = g_partial[threadIdx.x];
    __syncthreads();
    #pragma unroll
    for (int s = 512; s > 0; s >>= 1) {
        if (threadIdx.x < s) red[threadIdx.x] = fmaxf(red[threadIdx.x], red[threadIdx.x + s]);
        __syncthreads();
    }
    if (threadIdx.x == 0) {
        float sc = __fdiv_rn(red[0], 127.0f);
        g_scale = sc;
        g_inv = __fdiv_rn(1.0f, sc);
    }
}

// ===================== stage 2: fused quantize-x + weight-convert =====================
// blocks [0, HALF): quantize x -> int8;  blocks [HALF, 2*HALF): int32 w -> int8
__global__ void k_prep(const float* __restrict__ x, const int* __restrict__ w) {
    const int HALF = 1024;
    const int n4 = T * IN_F / 4;
    if (blockIdx.x < HALF) {
        const float inv = g_inv;
        const float4* x4 = (const float4*)x;
        uint32_t* o = (uint32_t*)g_qx;
        for (int i = blockIdx.x * blockDim.x + threadIdx.x; i < n4; i += HALF * blockDim.x) {
            float4 v = x4[i];
            // |x*inv| <= 127*(1+eps): round-to-nearest lands in [-127,127], no clamp.
            int q0 = __float2int_rn(v.x * inv);
            int q1 = __float2int_rn(v.y * inv);
            int q2 = __float2int_rn(v.z * inv);
            int q3 = __float2int_rn(v.w * inv);
            o[i] = (q0 & 0xFF) | ((q1 & 0xFF) << 8) | ((q2 & 0xFF) << 16) | ((uint32_t)(q3 & 0xFF) << 24);
        }
    } else {
        const int4* w4 = (const int4*)w;
        uint32_t* o = (uint32_t*)g_wt;
        for (int i = (blockIdx.x - HALF) * blockDim.x + threadIdx.x; i < n4; i += HALF * blockDim.x) {
            int4 v = w4[i];
            o[i] = (v.x & 0xFF) | ((v.y & 0xFF) << 8) | ((v.z & 0xFF) << 16) | ((uint32_t)(v.w & 0xFF) << 24);
        }
    }
}

// ===================== stage 3: int8 mma.sync GEMM, 4-stage cp.async =====================
// CTA 128x128, 8 warps in 2(M) x 4(N), warp tile 64x32, 2 CTAs/SM.
__global__ void __launch_bounds__(256, 2) k_gemm(const float* __restrict__ wscale,
                                                 const float* __restrict__ bias,
                                                 float* __restrict__ out) {
    extern __shared__ __align__(16) char smem[];
    const uint32_t sbase = smem_u32(smem);

    const int tid  = threadIdx.x;
    const int lane = tid & 31;
    const int wid  = tid >> 5;
    const int mwarp = wid >> 2;     // 0..1
    const int nwarp = wid & 3;      // 0..3
    const int Mbase = blockIdx.y * 128;
    const int Nbase = blockIdx.x * 128;

    // per-thread staging: A rows r0, r0+64 -> smem rows r0, r0+64
    //                     B rows r0, r0+64 -> smem rows 128+r0, 192+r0
    const int r0 = tid >> 2;             // 0..63
    const int cb = (tid & 3) * 16;       // byte col in 64B chunk
    const int8_t* gA0 = g_qx + (size_t)(Mbase + r0)      * IN_F + cb;
    const int8_t* gA1 = g_qx + (size_t)(Mbase + r0 + 64) * IN_F + cb;
    const int8_t* gB0 = g_wt + (size_t)(Nbase + r0)      * IN_F + cb;
    const int8_t* gB1 = g_wt + (size_t)(Nbase + r0 + 64) * IN_F + cb;
    const uint32_t sA0 = sbase + (uint32_t)r0 * ROWB + cb;
    const uint32_t sA1 = sA0 + 64u * ROWB;
    const uint32_t sB0 = sA0 + 128u * ROWB;
    const uint32_t sB1 = sA0 + 192u * ROWB;

    // ldmatrix per-thread offsets (relative to stage base)
    const int tile = lane >> 3;
    const int sub  = lane & 7;
    uint32_t aoff[4], boff[2];
    #pragma unroll
    for (int mb = 0; mb < 4; ++mb)
        aoff[mb] = sbase + (uint32_t)(mwarp * 64 + mb * 16 + (tile & 1) * 8 + sub) * ROWB
                 + (uint32_t)(tile >> 1) * 16;
    #pragma unroll
    for (int p = 0; p < 2; ++p)
        boff[p] = sbase + (uint32_t)(128 + nwarp * 32 + p * 16 + (tile >> 1) * 8 + sub) * ROWB
                 + (uint32_t)(tile & 1) * 16;

    int acc[4][4][4];
    #pragma unroll
    for (int mb = 0; mb < 4; ++mb)
        #pragma unroll
        for (int nb = 0; nb < 4; ++nb)
            #pragma unroll
            for (int f = 0; f < 4; ++f) acc[mb][nb][f] = 0;

    // prologue: issue stages 0..2
    #pragma unroll
    for (int s = 0; s < STAGES - 1; ++s) {
        const uint32_t so = (uint32_t)s * SSTR;
        const int ko = s * KC;
        cp16(sA0 + so, gA0 + ko);
        cp16(sA1 + so, gA1 + ko);
        cp16(sB0 + so, gB0 + ko);
        cp16(sB1 + so, gB1 + ko);
        cp_commit();
    }

    for (int it = 0; it < KITERS; ++it) {
        cp_wait2();                 // stage it landed
        __syncthreads();            // visible to all; all warps done with stage it-1

        // issue stage it+3 (overwrites slot of stage it-1, safe after the barrier)
        if (it + STAGES - 1 < KITERS) {
            const uint32_t so = (uint32_t)((it + STAGES - 1) & (STAGES - 1)) * SSTR;
            const int ko = (it + STAGES - 1) * KC;
            cp16(sA0 + so, gA0 + ko);
            cp16(sA1 + so, gA1 + ko);
            cp16(sB0 + so, gB0 + ko);
            cp16(sB1 + so, gB1 + ko);
        }
        cp_commit();                // commit every iter (empty at tail) to keep group counts uniform

        const uint32_t so = (uint32_t)(it & (STAGES - 1)) * SSTR;
        #pragma unroll
        for (int ks = 0; ks < 2; ++ks) {
            uint32_t af[4][4];
            uint32_t bf[4][2];
            #pragma unroll
            for (int mb = 0; mb < 4; ++mb)
                ldsm_x4(af[mb], aoff[mb] + so + ks * 32);
            #pragma unroll
            for (int p = 0; p < 2; ++p) {
                uint32_t r[4];
                ldsm_x4(r, boff[p] + so + ks * 32);
                bf[p * 2 + 0][0] = r[0]; bf[p * 2 + 0][1] = r[1];
                bf[p * 2 + 1][0] = r[2]; bf[p * 2 + 1][1] = r[3];
            }
            #pragma unroll
            for (int mb = 0; mb < 4; ++mb)
                #pragma unroll
                for (int nb = 0; nb < 4; ++nb)
                    mma_s8(acc[mb][nb], af[mb], bf[nb]);
        }
    }

    // epilogue: exact int32 -> fp32 scale + bias, direct coalesced-enough float2 stores
    const float s = g_scale * wscale[0];
    const int g   = lane >> 2;
    const int tg2 = (lane & 3) * 2;
    #pragma unroll
    for (int nb = 0; nb < 4; ++nb) {
        const int col = Nbase + nwarp * 32 + nb * 8 + tg2;
        const float2 bb = *(const float2*)(bias + col);
        #pragma unroll
        for (int mb = 0; mb < 4; ++mb) {
            const int row = Mbase + mwarp * 64 + mb * 16 + g;
            float2 v0, v1;
            v0.x = fmaf((float)acc[mb][nb][0], s, bb.x);
            v0.y = fmaf((float)acc[mb][nb][1], s, bb.y);
            v1.x = fmaf((float)acc[mb][nb][2], s, bb.x);
            v1.y = fmaf((float)acc[mb][nb][3], s, bb.y);
            *(float2*)(out + (size_t)row * OUT_F + col)       = v0;
            *(float2*)(out + (size_t)(row + 8) * OUT_F + col) = v1;
        }
    }
}

// ===================== launch =====================
extern "C" void kernel_launch(void* const* d_in, const int* in_sizes, int n_in,
                              void* d_out, int out_size) {
    const float* x    = (const float*)d_in[0];
    const int*   qw   = (const int*)d_in[1];
    const float* ws   = (const float*)d_in[2];
    const float* bias = (const float*)d_in[3];
    float* out = (float*)d_out;

    k_maxabs<<<1024, 256>>>(x);
    k_finalize<<<1, 1024>>>();
    k_prep<<<2048, 256>>>(x, qw);
    cudaFuncSetAttribute(k_gemm, cudaFuncAttributeMaxDynamicSharedMemorySize, SMEM_TOTAL);
    k_gemm<<<dim3(OUT_F / 128, T / 128), 256, SMEM_TOTAL>>>(ws, bias, out);
}